// round 7
// baseline (speedup 1.0000x reference)
#include <cuda_runtime.h>
#include <cuda_fp16.h>

#define SB   32      // S*B
#define NTOK 2048    // N
#define KK   16      // K
#define DD   32      // D
#define HH   128     // H

#define TPB   256    // threads per block (8 warps)
#define TOKPB 32     // tokens per block (1 per lane; warp = h-slice of 16)

typedef unsigned long long u64;

// Scratch for hk[k,h] + b1[h] per (s,b). 32*16*128 floats = 256 KB.
__device__ float g_hkb[SB * KK * HH];

__device__ __forceinline__ u64 pk2(float lo, float hi) {
    u64 r; asm("mov.b64 %0, {%1, %2};" : "=l"(r) : "f"(lo), "f"(hi)); return r;
}
__device__ __forceinline__ void upk2(float& lo, float& hi, u64 v) {
    asm("mov.b64 {%0, %1}, %2;" : "=f"(lo), "=f"(hi) : "l"(v));
}
__device__ __forceinline__ u64 add2(u64 a, u64 b) {
    u64 r; asm("add.rn.f32x2 %0, %1, %2;" : "=l"(r) : "l"(a), "l"(b)); return r;
}
__device__ __forceinline__ u64 fma2(u64 a, u64 b, u64 c) {
    u64 r; asm("fma.rn.f32x2 %0, %1, %2, %3;" : "=l"(r) : "l"(a), "l"(b), "l"(c)); return r;
}
// tanh on a packed half2 — one MUFU op for two values.
__device__ __forceinline__ __half2 tanh2(__half2 v) {
    unsigned vi = *reinterpret_cast<unsigned*>(&v), yi;
    asm("tanh.approx.f16x2 %0, %1;" : "=r"(yi) : "r"(vi));
    return *reinterpret_cast<__half2*>(&yi);
}

// ---------------------------------------------------------------------------
// Prep: hkb[sb,k,h] = sum_d mu[sb,k,d]*Wm[d,h] + tau[sb,k,d]*Wt[d,h] + b1[h]
// ---------------------------------------------------------------------------
__global__ void prep_kernel(const float* __restrict__ mu,
                            const float* __restrict__ tau,
                            const float* __restrict__ W1,
                            const float* __restrict__ b1) {
    int k  = blockIdx.x;
    int sb = blockIdx.y;
    int h  = threadIdx.x;
    const float* mur  = mu  + (sb * KK + k) * DD;
    const float* taur = tau + (sb * KK + k) * DD;
    float s = b1[h];
    #pragma unroll
    for (int d = 0; d < DD; d++) {
        s = fmaf(mur [d], W1[(DD     + d) * HH + h], s);
        s = fmaf(taur[d], W1[(2 * DD + d) * HH + h], s);
    }
    g_hkb[(sb * KK + k) * HH + h] = s;
}

// ---------------------------------------------------------------------------
// Main: block = 8 warps x 32 tokens. Warp w owns h-slice [16w, 16w+16);
// lane = token. Small slice -> ~55 live regs -> 32 warps/SM resident.
//   Phase A (f32): hx2[8] via 8 independent FFMA2 chains.
//   Phase B: per k: 4 broadcast LDS.128 + 8 ADD2 (f32) + 8 F2FP pack
//            + 8 tanh.f16x2 + 8 HFMA2 into 4 half2 accs.
// ---------------------------------------------------------------------------
__global__ __launch_bounds__(TPB, 4)
void main_kernel(const float* __restrict__ x,
                 const float* __restrict__ W1,
                 const float* __restrict__ W2,
                 float* __restrict__ out) {
    __shared__ float Wx_s[DD * HH];             // 16 KB
    __shared__ float hkb_s[KK * HH];            //  8 KB
    __shared__ float w2_s[HH];                  // 0.5 KB
    __shared__ float part_s[8][TOKPB][KK + 1];  // 17.4 KB, padded rows

    const int tid  = threadIdx.x;
    const int w    = tid >> 5;                  // warp id = h-slice (0..7)
    const int lane = tid & 31;                  // token within block
    const int sb   = blockIdx.y;
    const int n    = blockIdx.x * TOKPB + lane;

    for (int i = tid; i < DD * HH; i += TPB) Wx_s[i]  = W1[i];   // rows 0..31 of W1
    for (int i = tid; i < KK * HH; i += TPB) hkb_s[i] = g_hkb[sb * KK * HH + i];
    if (tid < HH) w2_s[tid] = W2[tid];
    __syncthreads();

    // x row (32 floats) into registers
    float xr[DD];
    const float4* xp = reinterpret_cast<const float4*>(x + ((size_t)sb * NTOK + n) * DD);
    #pragma unroll
    for (int i = 0; i < 8; i++) {
        float4 v = xp[i];
        xr[4 * i + 0] = v.x; xr[4 * i + 1] = v.y;
        xr[4 * i + 2] = v.z; xr[4 * i + 3] = v.w;
    }

    const int h0 = w * 16;

    // ---- Phase A: hx for the 16-h slice (8 f32x2 chains) ----
    u64 hx2[8];
    #pragma unroll
    for (int j = 0; j < 8; j++) hx2[j] = 0ull;

    #pragma unroll
    for (int d = 0; d < DD; d++) {
        u64 xd2 = pk2(xr[d], xr[d]);
        const ulonglong2* wrow = reinterpret_cast<const ulonglong2*>(&Wx_s[d * HH + h0]);
        #pragma unroll
        for (int q = 0; q < 4; q++) {
            ulonglong2 wv = wrow[q];          // warp-uniform broadcast LDS.128
            hx2[2 * q + 0] = fma2(xd2, wv.x, hx2[2 * q + 0]);
            hx2[2 * q + 1] = fma2(xd2, wv.y, hx2[2 * q + 1]);
        }
    }

    // W2 slice as half2 pairs
    __half2 w2h[8];
    {
        const float4* w2p = reinterpret_cast<const float4*>(&w2_s[h0]);
        #pragma unroll
        for (int q = 0; q < 4; q++) {
            float4 wv = w2p[q];
            w2h[2 * q + 0] = __floats2half2_rn(wv.x, wv.y);
            w2h[2 * q + 1] = __floats2half2_rn(wv.z, wv.w);
        }
    }

    // ---- Phase B: k-sweep, tanh in f16x2 ----
    float acc[KK];
    #pragma unroll
    for (int k = 0; k < KK; k++) {
        const ulonglong2* hkp = reinterpret_cast<const ulonglong2*>(&hkb_s[k * HH + h0]);
        __half2 a0 = __float2half2_rn(0.f), a1 = a0, a2 = a0, a3 = a0;
        #pragma unroll
        for (int q = 0; q < 4; q++) {
            ulonglong2 hv = hkp[q];           // warp-uniform broadcast LDS.128
            u64 t0 = add2(hx2[2 * q + 0], hv.x);   // f32 precision sum
            u64 t1 = add2(hx2[2 * q + 1], hv.y);
            float l0, g0, l1, g1;
            upk2(l0, g0, t0);
            upk2(l1, g1, t1);
            __half2 th0 = tanh2(__floats2half2_rn(l0, g0));
            __half2 th1 = tanh2(__floats2half2_rn(l1, g1));
            if (q & 1) { a2 = __hfma2(th0, w2h[2 * q + 0], a2);
                         a3 = __hfma2(th1, w2h[2 * q + 1], a3); }
            else       { a0 = __hfma2(th0, w2h[2 * q + 0], a0);
                         a1 = __hfma2(th1, w2h[2 * q + 1], a1); }
        }
        float2 f01 = __half22float2(__hadd2(a0, a1));
        float2 f23 = __half22float2(__hadd2(a2, a3));
        acc[k] = (f01.x + f01.y) + (f23.x + f23.y);
    }

    // Stage partial gammas (scalar, padded row of 17 -> conflict-light).
    #pragma unroll
    for (int k = 0; k < KK; k++) part_s[w][lane][k] = acc[k];
    __syncthreads();

    // Reduce + softmax: thread t handles token (t>>3), k-pair (t&7).
    const int tok = tid >> 3;                   // 0..31
    const int kp  = tid & 7;                    // 0..7 -> k = 2kp, 2kp+1
    float g0 = 0.f, g1 = 0.f;
    #pragma unroll
    for (int ww = 0; ww < 8; ww++) {
        g0 += part_s[ww][tok][2 * kp + 0];
        g1 += part_s[ww][tok][2 * kp + 1];
    }

    // max over 16 k: local max of 2, butterfly across 8 lanes of this token
    float m = fmaxf(g0, g1);
    m = fmaxf(m, __shfl_xor_sync(0xffffffffu, m, 1));
    m = fmaxf(m, __shfl_xor_sync(0xffffffffu, m, 2));
    m = fmaxf(m, __shfl_xor_sync(0xffffffffu, m, 4));

    float e0 = __expf(g0 - m), e1 = __expf(g1 - m);
    float s = e0 + e1;
    s += __shfl_xor_sync(0xffffffffu, s, 1);
    s += __shfl_xor_sync(0xffffffffu, s, 2);
    s += __shfl_xor_sync(0xffffffffu, s, 4);
    float inv = __fdividef(1.f, s);

    const int ntok = blockIdx.x * TOKPB + tok;
    float2 o;
    o.x = e0 * inv; o.y = e1 * inv;
    reinterpret_cast<float2*>(out + ((size_t)sb * NTOK + ntok) * KK)[kp] = o;
}

extern "C" void kernel_launch(void* const* d_in, const int* in_sizes, int n_in,
                              void* d_out, int out_size) {
    const float* x   = (const float*)d_in[0];
    const float* mu  = (const float*)d_in[1];
    const float* tau = (const float*)d_in[2];
    const float* W1  = (const float*)d_in[3];
    const float* b1  = (const float*)d_in[4];
    const float* W2  = (const float*)d_in[5];
    // d_in[6] = b2: cancels in softmax, unused.
    float* out = (float*)d_out;

    prep_kernel<<<dim3(KK, SB), HH>>>(mu, tau, W1, b1);
    main_kernel<<<dim3(NTOK / TOKPB, SB), TPB>>>(x, W1, W2, out);
}

// round 8
// speedup vs baseline: 1.0727x; 1.0727x over previous
#include <cuda_runtime.h>
#include <cuda_fp16.h>

#define SB   32      // S*B
#define NTOK 2048    // N
#define KK   16      // K
#define DD   32      // D
#define HH   128     // H

#define TPB   256    // threads per block (8 warps)
#define TOKPB 128    // tokens per block
#define NW    8      // warps per block (warp = 16-h slice)
#define TT    4      // token-groups per thread (lane covers 32 tokens each)

typedef unsigned long long u64;

// Scratch for hk[k,h] + b1[h] per (s,b). 32*16*128 floats = 256 KB.
__device__ float g_hkb[SB * KK * HH];

__device__ __forceinline__ u64 pk2(float lo, float hi) {
    u64 r; asm("mov.b64 %0, {%1, %2};" : "=l"(r) : "f"(lo), "f"(hi)); return r;
}
__device__ __forceinline__ void upk2(float& lo, float& hi, u64 v) {
    asm("mov.b64 {%0, %1}, %2;" : "=f"(lo), "=f"(hi) : "l"(v));
}
__device__ __forceinline__ u64 add2(u64 a, u64 b) {
    u64 r; asm("add.rn.f32x2 %0, %1, %2;" : "=l"(r) : "l"(a), "l"(b)); return r;
}
__device__ __forceinline__ u64 fma2(u64 a, u64 b, u64 c) {
    u64 r; asm("fma.rn.f32x2 %0, %1, %2, %3;" : "=l"(r) : "l"(a), "l"(b), "l"(c)); return r;
}
__device__ __forceinline__ __half2 tanh2(__half2 v) {
    unsigned vi = *reinterpret_cast<unsigned*>(&v), yi;
    asm("tanh.approx.f16x2 %0, %1;" : "=r"(yi) : "r"(vi));
    return *reinterpret_cast<__half2*>(&yi);
}

// ---------------------------------------------------------------------------
// Prep: hkb[sb,k,h] = sum_d mu[sb,k,d]*Wm[d,h] + tau[sb,k,d]*Wt[d,h] + b1[h]
// ---------------------------------------------------------------------------
__global__ void prep_kernel(const float* __restrict__ mu,
                            const float* __restrict__ tau,
                            const float* __restrict__ W1,
                            const float* __restrict__ b1) {
    int k  = blockIdx.x;
    int sb = blockIdx.y;
    int h  = threadIdx.x;
    const float* mur  = mu  + (sb * KK + k) * DD;
    const float* taur = tau + (sb * KK + k) * DD;
    float s = b1[h];
    #pragma unroll
    for (int d = 0; d < DD; d++) {
        s = fmaf(mur [d], W1[(DD     + d) * HH + h], s);
        s = fmaf(taur[d], W1[(2 * DD + d) * HH + h], s);
    }
    g_hkb[(sb * KK + k) * HH + h] = s;
}

// ---------------------------------------------------------------------------
// Main: block = 8 warps x 128 tokens. Warp w owns h-slice [16w,16w+16);
// lane = token-in-group; each thread register-blocks TT=4 token groups, so
// every Wx / hkb smem broadcast feeds 4x the FMAs (operand-delivery bound /4).
// Phase B finalizes k in chunks of 2 with an interleaved smem reduction.
// ---------------------------------------------------------------------------
__global__ __launch_bounds__(TPB, 2)
void main_kernel(const float* __restrict__ x,
                 const float* __restrict__ W1,
                 const float* __restrict__ W2,
                 float* __restrict__ out) {
    __shared__ float Wx_s[DD * HH];              // 16 KB
    __shared__ float hkb_s[KK * HH];             //  8 KB
    __shared__ float w2_s[HH];                   // 0.5 KB
    __shared__ float xT_s[16][TOKPB];            //  8 KB (one d-half, transposed)
    __shared__ float part_s[NW][TOKPB][3];       // 12.75 KB (k-chunk 2 + pad)

    const int tid  = threadIdx.x;
    const int w    = tid >> 5;                   // warp id = h-slice (0..7)
    const int lane = tid & 31;                   // token within group
    const int sb   = blockIdx.y;
    const int tokb = blockIdx.x * TOKPB;

    for (int i = tid; i < DD * HH; i += TPB) Wx_s[i]  = W1[i];   // rows 0..31
    for (int i = tid; i < KK * HH; i += TPB) hkb_s[i] = g_hkb[sb * KK * HH + i];
    if (tid < HH) w2_s[tid] = W2[tid];

    const int h0 = w * 16;

    // ---- Phase A: hx for TT=4 token groups x 16 h, d staged in two halves ----
    u64 hx2[TT][8];
    #pragma unroll
    for (int t = 0; t < TT; t++)
        #pragma unroll
        for (int j = 0; j < 8; j++) hx2[t][j] = 0ull;

    #pragma unroll 1
    for (int dh = 0; dh < 2; dh++) {
        __syncthreads();   // (dh=0: also fences the cooperative fills above)
        // stage xT_s[dl][tok] = x[tokb+tok][dh*16+dl]  (coalesced LDG.128)
        #pragma unroll
        for (int it = 0; it < 2; it++) {
            int idx = tid + it * TPB;            // 0..511
            int tok = idx >> 2, q = idx & 3;
            float4 v = *reinterpret_cast<const float4*>(
                x + ((size_t)sb * NTOK + tokb + tok) * DD + dh * 16 + q * 4);
            xT_s[q * 4 + 0][tok] = v.x; xT_s[q * 4 + 1][tok] = v.y;
            xT_s[q * 4 + 2][tok] = v.z; xT_s[q * 4 + 3][tok] = v.w;
        }
        __syncthreads();

        #pragma unroll
        for (int dl = 0; dl < 16; dl++) {
            const int d = dh * 16 + dl;
            const ulonglong2* wrow = reinterpret_cast<const ulonglong2*>(&Wx_s[d * HH + h0]);
            ulonglong2 wa = wrow[0], wb = wrow[1], wc = wrow[2], wd = wrow[3];
            #pragma unroll
            for (int t = 0; t < TT; t++) {
                float xv = xT_s[dl][t * 32 + lane];   // conflict-free LDS.32
                u64 x2 = pk2(xv, xv);
                hx2[t][0] = fma2(x2, wa.x, hx2[t][0]);
                hx2[t][1] = fma2(x2, wa.y, hx2[t][1]);
                hx2[t][2] = fma2(x2, wb.x, hx2[t][2]);
                hx2[t][3] = fma2(x2, wb.y, hx2[t][3]);
                hx2[t][4] = fma2(x2, wc.x, hx2[t][4]);
                hx2[t][5] = fma2(x2, wc.y, hx2[t][5]);
                hx2[t][6] = fma2(x2, wd.x, hx2[t][6]);
                hx2[t][7] = fma2(x2, wd.y, hx2[t][7]);
            }
        }
    }

    // W2 slice as half2 pairs
    __half2 w2h[8];
    {
        const float4* w2p = reinterpret_cast<const float4*>(&w2_s[h0]);
        #pragma unroll
        for (int q = 0; q < 4; q++) {
            float4 wv = w2p[q];
            w2h[2 * q + 0] = __floats2half2_rn(wv.x, wv.y);
            w2h[2 * q + 1] = __floats2half2_rn(wv.z, wv.w);
        }
    }

    // ---- Phase B: 8 rounds of 2 k, compute + interleaved reduction ----
    float g[8];
    const int rtok  = tid >> 1;                  // reducer token (0..127)
    const int khalf = tid & 1;                   // k 0-7 vs 8-15

    #pragma unroll 1
    for (int r = 0; r < 8; r++) {
        #pragma unroll
        for (int kk = 0; kk < 2; kk++) {
            const int k = r * 2 + kk;
            const ulonglong2* hkp = reinterpret_cast<const ulonglong2*>(&hkb_s[k * HH + h0]);
            ulonglong2 ha = hkp[0], hb = hkp[1], hc = hkp[2], hd = hkp[3];
            #pragma unroll
            for (int t = 0; t < TT; t++) {
                u64 s0 = add2(hx2[t][0], ha.x);
                u64 s1 = add2(hx2[t][1], ha.y);
                u64 s2 = add2(hx2[t][2], hb.x);
                u64 s3 = add2(hx2[t][3], hb.y);
                u64 s4 = add2(hx2[t][4], hc.x);
                u64 s5 = add2(hx2[t][5], hc.y);
                u64 s6 = add2(hx2[t][6], hd.x);
                u64 s7 = add2(hx2[t][7], hd.y);
                float f0, f1, f2, f3, f4, f5, f6, f7;
                __half2 a0 = __float2half2_rn(0.f), a1 = a0, a2 = a0, a3 = a0;
                upk2(f0, f1, s0); upk2(f2, f3, s1);
                a0 = __hfma2(tanh2(__floats2half2_rn(f0, f1)), w2h[0], a0);
                a1 = __hfma2(tanh2(__floats2half2_rn(f2, f3)), w2h[1], a1);
                upk2(f4, f5, s2); upk2(f6, f7, s3);
                a2 = __hfma2(tanh2(__floats2half2_rn(f4, f5)), w2h[2], a2);
                a3 = __hfma2(tanh2(__floats2half2_rn(f6, f7)), w2h[3], a3);
                upk2(f0, f1, s4); upk2(f2, f3, s5);
                a0 = __hfma2(tanh2(__floats2half2_rn(f0, f1)), w2h[4], a0);
                a1 = __hfma2(tanh2(__floats2half2_rn(f2, f3)), w2h[5], a1);
                upk2(f4, f5, s6); upk2(f6, f7, s7);
                a2 = __hfma2(tanh2(__floats2half2_rn(f4, f5)), w2h[6], a2);
                a3 = __hfma2(tanh2(__floats2half2_rn(f6, f7)), w2h[7], a3);
                float2 f01 = __half22float2(__hadd2(a0, a1));
                float2 f23 = __half22float2(__hadd2(a2, a3));
                part_s[w][t * 32 + lane][kk] = (f01.x + f01.y) + (f23.x + f23.y);
            }
        }
        __syncthreads();
        if ((khalf == 0) == (r < 4)) {
            #pragma unroll
            for (int kk = 0; kk < 2; kk++) {
                float s = 0.f;
                #pragma unroll
                for (int ww = 0; ww < NW; ww++) s += part_s[ww][rtok][kk];
                g[(r & 3) * 2 + kk] = s;
            }
        }
        __syncthreads();
    }

    // ---- Softmax: thread (rtok, khalf) holds k = khalf*8 + 0..7 ----
    float m = g[0];
    #pragma unroll
    for (int i = 1; i < 8; i++) m = fmaxf(m, g[i]);
    m = fmaxf(m, __shfl_xor_sync(0xffffffffu, m, 1));

    float s = 0.f;
    #pragma unroll
    for (int i = 0; i < 8; i++) { g[i] = __expf(g[i] - m); s += g[i]; }
    s += __shfl_xor_sync(0xffffffffu, s, 1);
    float inv = __fdividef(1.f, s);

    float* op = out + ((size_t)sb * NTOK + tokb + rtok) * KK + khalf * 8;
    float4 o0, o1;
    o0.x = g[0] * inv; o0.y = g[1] * inv; o0.z = g[2] * inv; o0.w = g[3] * inv;
    o1.x = g[4] * inv; o1.y = g[5] * inv; o1.z = g[6] * inv; o1.w = g[7] * inv;
    reinterpret_cast<float4*>(op)[0] = o0;
    reinterpret_cast<float4*>(op)[1] = o1;
}

extern "C" void kernel_launch(void* const* d_in, const int* in_sizes, int n_in,
                              void* d_out, int out_size) {
    const float* x   = (const float*)d_in[0];
    const float* mu  = (const float*)d_in[1];
    const float* tau = (const float*)d_in[2];
    const float* W1  = (const float*)d_in[3];
    const float* b1  = (const float*)d_in[4];
    const float* W2  = (const float*)d_in[5];
    // d_in[6] = b2: cancels in softmax, unused.
    float* out = (float*)d_out;

    prep_kernel<<<dim3(KK, SB), HH>>>(mu, tau, W1, b1);
    main_kernel<<<dim3(NTOK / TOKPB, SB), TPB>>>(x, W1, W2, out);
}

// round 9
// speedup vs baseline: 1.0834x; 1.0100x over previous
#include <cuda_runtime.h>
#include <cuda_fp16.h>

#define SB   32      // S*B
#define NTOK 2048    // N
#define KK   16      // K
#define DD   32      // D
#define HH   128     // H

#define TPB   256    // threads per block (8 warps)
#define TOKPB 128    // tokens per block
#define NW    8      // warps per block (warp = 16-h slice)
#define TT    4      // token-groups per thread

typedef unsigned long long u64;

// hk[k,h]+b1[h] per (s,b), packed half2 (h pairs). 32*16*64 u32 = 128 KB.
__device__ unsigned g_hkbh[SB * KK * (HH / 2)];

__device__ __forceinline__ u64 pk2(float lo, float hi) {
    u64 r; asm("mov.b64 %0, {%1, %2};" : "=l"(r) : "f"(lo), "f"(hi)); return r;
}
__device__ __forceinline__ void upk2(float& lo, float& hi, u64 v) {
    asm("mov.b64 {%0, %1}, %2;" : "=f"(lo), "=f"(hi) : "l"(v));
}
__device__ __forceinline__ u64 fma2(u64 a, u64 b, u64 c) {
    u64 r; asm("fma.rn.f32x2 %0, %1, %2, %3;" : "=l"(r) : "l"(a), "l"(b), "l"(c)); return r;
}
__device__ __forceinline__ __half2 tanh2(__half2 v) {
    unsigned vi = *reinterpret_cast<unsigned*>(&v), yi;
    asm("tanh.approx.f16x2 %0, %1;" : "=r"(yi) : "r"(vi));
    return *reinterpret_cast<__half2*>(&yi);
}
__device__ __forceinline__ __half2 asH2(unsigned u) { return *reinterpret_cast<__half2*>(&u); }
__device__ __forceinline__ unsigned h2bits(__half2 h) { return *reinterpret_cast<unsigned*>(&h); }

// ---------------------------------------------------------------------------
// Prep: hkbh[sb,k,h/2] = half2( sum_d mu*Wm + tau*Wt + b1 ) for h pair.
// 64 threads per (k,sb), 128 FMA each.
// ---------------------------------------------------------------------------
__global__ void prep_kernel(const float* __restrict__ mu,
                            const float* __restrict__ tau,
                            const float* __restrict__ W1,
                            const float* __restrict__ b1) {
    int k  = blockIdx.x;
    int sb = blockIdx.y;
    int t  = threadIdx.x;               // 0..63 -> h pair (2t, 2t+1)
    const float* mur  = mu  + (sb * KK + k) * DD;
    const float* taur = tau + (sb * KK + k) * DD;
    int h0 = 2 * t, h1 = 2 * t + 1;
    float s0 = b1[h0], s1 = b1[h1];
    #pragma unroll
    for (int d = 0; d < DD; d++) {
        float m = mur[d], ta = taur[d];
        s0 = fmaf(m,  W1[(DD     + d) * HH + h0], s0);
        s1 = fmaf(m,  W1[(DD     + d) * HH + h1], s1);
        s0 = fmaf(ta, W1[(2 * DD + d) * HH + h0], s0);
        s1 = fmaf(ta, W1[(2 * DD + d) * HH + h1], s1);
    }
    g_hkbh[(sb * KK + k) * (HH / 2) + t] = h2bits(__floats2half2_rn(s0, s1));
}

// ---------------------------------------------------------------------------
// Main: block = 8 warps x 128 tokens; warp w owns h-slice [16w,16w+16);
// thread register-blocks TT=4 token groups. Phase A in f32 (FFMA2), hx then
// converted ONCE to half2; phase B inner loop is pure f16:
//   HADD2 -> tanh.f16x2 -> HFMA2  (no cvt in the hot loop).
// ---------------------------------------------------------------------------
__global__ __launch_bounds__(TPB, 2)
void main_kernel(const float* __restrict__ x,
                 const float* __restrict__ W1,
                 const float* __restrict__ W2,
                 float* __restrict__ out) {
    __shared__ float    Wx_s[DD * HH];           // 16 KB
    __shared__ unsigned hkb_s[KK * (HH / 2)];    //  4 KB (half2)
    __shared__ float    w2_s[HH];                // 0.5 KB
    __shared__ float    xT_s[16][TOKPB];         //  8 KB (one d-half, transposed)
    __shared__ float    part_s[NW][TOKPB][3];    // 12.75 KB

    const int tid  = threadIdx.x;
    const int w    = tid >> 5;                   // warp id = h-slice (0..7)
    const int lane = tid & 31;
    const int sb   = blockIdx.y;
    const int tokb = blockIdx.x * TOKPB;

    for (int i = tid; i < DD * HH; i += TPB) Wx_s[i] = W1[i];           // rows 0..31
    for (int i = tid; i < KK * (HH / 2); i += TPB) hkb_s[i] = g_hkbh[sb * KK * (HH / 2) + i];
    if (tid < HH) w2_s[tid] = W2[tid];

    const int h0 = w * 16;

    // ---- Phase A: hx (f32) for TT token groups x 16 h ----
    u64 hx2[TT][8];
    #pragma unroll
    for (int t = 0; t < TT; t++)
        #pragma unroll
        for (int j = 0; j < 8; j++) hx2[t][j] = 0ull;

    #pragma unroll 1
    for (int dh = 0; dh < 2; dh++) {
        __syncthreads();   // dh=0 also fences the cooperative fills
        #pragma unroll
        for (int it = 0; it < 2; it++) {
            int idx = tid + it * TPB;            // 0..511
            int tok = idx >> 2, q = idx & 3;
            float4 v = *reinterpret_cast<const float4*>(
                x + ((size_t)sb * NTOK + tokb + tok) * DD + dh * 16 + q * 4);
            xT_s[q * 4 + 0][tok] = v.x; xT_s[q * 4 + 1][tok] = v.y;
            xT_s[q * 4 + 2][tok] = v.z; xT_s[q * 4 + 3][tok] = v.w;
        }
        __syncthreads();

        #pragma unroll
        for (int dl = 0; dl < 16; dl++) {
            const int d = dh * 16 + dl;
            const ulonglong2* wrow = reinterpret_cast<const ulonglong2*>(&Wx_s[d * HH + h0]);
            ulonglong2 wa = wrow[0], wb = wrow[1], wc = wrow[2], wd = wrow[3];
            #pragma unroll
            for (int t = 0; t < TT; t++) {
                float xv = xT_s[dl][t * 32 + lane];
                u64 x2 = pk2(xv, xv);
                hx2[t][0] = fma2(x2, wa.x, hx2[t][0]);
                hx2[t][1] = fma2(x2, wa.y, hx2[t][1]);
                hx2[t][2] = fma2(x2, wb.x, hx2[t][2]);
                hx2[t][3] = fma2(x2, wb.y, hx2[t][3]);
                hx2[t][4] = fma2(x2, wc.x, hx2[t][4]);
                hx2[t][5] = fma2(x2, wc.y, hx2[t][5]);
                hx2[t][6] = fma2(x2, wd.x, hx2[t][6]);
                hx2[t][7] = fma2(x2, wd.y, hx2[t][7]);
            }
        }
    }

    // One-time hx -> half2 (32 cvts, amortized over the 16-k sweep)
    unsigned hxh[TT][8];
    #pragma unroll
    for (int t = 0; t < TT; t++)
        #pragma unroll
        for (int q = 0; q < 8; q++) {
            float lo, hi;
            upk2(lo, hi, hx2[t][q]);
            hxh[t][q] = h2bits(__floats2half2_rn(lo, hi));
        }

    // W2 slice as half2 pairs
    __half2 w2h[8];
    {
        const float4* w2p = reinterpret_cast<const float4*>(&w2_s[h0]);
        #pragma unroll
        for (int q = 0; q < 4; q++) {
            float4 wv = w2p[q];
            w2h[2 * q + 0] = __floats2half2_rn(wv.x, wv.y);
            w2h[2 * q + 1] = __floats2half2_rn(wv.z, wv.w);
        }
    }

    // ---- Phase B: 8 rounds of 2 k, all-f16 inner loop + interleaved reduce ----
    float g[8];
    const int rtok  = tid >> 1;                  // reducer token (0..127)
    const int khalf = tid & 1;                   // k 0-7 vs 8-15

    #pragma unroll 1
    for (int r = 0; r < 8; r++) {
        #pragma unroll
        for (int kk = 0; kk < 2; kk++) {
            const int k = r * 2 + kk;
            const uint4* hkp = reinterpret_cast<const uint4*>(&hkb_s[k * (HH / 2) + w * 8]);
            uint4 hA = hkp[0], hB = hkp[1];      // 8 half2, warp-uniform
            #pragma unroll
            for (int t = 0; t < TT; t++) {
                __half2 a0, a1, a2, a3;
                a0 = __hmul2(tanh2(__hadd2(asH2(hxh[t][0]), asH2(hA.x))), w2h[0]);
                a1 = __hmul2(tanh2(__hadd2(asH2(hxh[t][1]), asH2(hA.y))), w2h[1]);
                a2 = __hmul2(tanh2(__hadd2(asH2(hxh[t][2]), asH2(hA.z))), w2h[2]);
                a3 = __hmul2(tanh2(__hadd2(asH2(hxh[t][3]), asH2(hA.w))), w2h[3]);
                a0 = __hfma2(tanh2(__hadd2(asH2(hxh[t][4]), asH2(hB.x))), w2h[4], a0);
                a1 = __hfma2(tanh2(__hadd2(asH2(hxh[t][5]), asH2(hB.y))), w2h[5], a1);
                a2 = __hfma2(tanh2(__hadd2(asH2(hxh[t][6]), asH2(hB.z))), w2h[6], a2);
                a3 = __hfma2(tanh2(__hadd2(asH2(hxh[t][7]), asH2(hB.w))), w2h[7], a3);
                float2 f01 = __half22float2(__hadd2(a0, a1));
                float2 f23 = __half22float2(__hadd2(a2, a3));
                part_s[w][t * 32 + lane][kk] = (f01.x + f01.y) + (f23.x + f23.y);
            }
        }
        __syncthreads();
        if ((khalf == 0) == (r < 4)) {
            #pragma unroll
            for (int kk = 0; kk < 2; kk++) {
                float s = 0.f;
                #pragma unroll
                for (int ww = 0; ww < NW; ww++) s += part_s[ww][rtok][kk];
                g[(r & 3) * 2 + kk] = s;
            }
        }
        __syncthreads();
    }

    // ---- Softmax: thread (rtok, khalf) holds k = khalf*8 + 0..7 ----
    float m = g[0];
    #pragma unroll
    for (int i = 1; i < 8; i++) m = fmaxf(m, g[i]);
    m = fmaxf(m, __shfl_xor_sync(0xffffffffu, m, 1));

    float s = 0.f;
    #pragma unroll
    for (int i = 0; i < 8; i++) { g[i] = __expf(g[i] - m); s += g[i]; }
    s += __shfl_xor_sync(0xffffffffu, s, 1);
    float inv = __fdividef(1.f, s);

    float* op = out + ((size_t)sb * NTOK + tokb + rtok) * KK + khalf * 8;
    float4 o0, o1;
    o0.x = g[0] * inv; o0.y = g[1] * inv; o0.z = g[2] * inv; o0.w = g[3] * inv;
    o1.x = g[4] * inv; o1.y = g[5] * inv; o1.z = g[6] * inv; o1.w = g[7] * inv;
    reinterpret_cast<float4*>(op)[0] = o0;
    reinterpret_cast<float4*>(op)[1] = o1;
}

extern "C" void kernel_launch(void* const* d_in, const int* in_sizes, int n_in,
                              void* d_out, int out_size) {
    const float* x   = (const float*)d_in[0];
    const float* mu  = (const float*)d_in[1];
    const float* tau = (const float*)d_in[2];
    const float* W1  = (const float*)d_in[3];
    const float* b1  = (const float*)d_in[4];
    const float* W2  = (const float*)d_in[5];
    // d_in[6] = b2: cancels in softmax, unused.
    float* out = (float*)d_out;

    prep_kernel<<<dim3(KK, SB), HH / 2>>>(mu, tau, W1, b1);
    main_kernel<<<dim3(NTOK / TOKPB, SB), TPB>>>(x, W1, W2, out);
}

// round 10
// speedup vs baseline: 1.2592x; 1.1622x over previous
#include <cuda_runtime.h>
#include <cuda_fp16.h>

#define SB   32      // S*B
#define NTOK 2048    // N
#define KK   16      // K
#define DD   32      // D
#define HH   128     // H

#define TPB   256    // threads per block (8 warps)
#define TOKPB 64     // tokens per block
#define NW    8      // warps (warp = 16-h slice)
#define TT    2      // token-groups per thread

typedef unsigned long long u64;

// hk[k,h]+b1[h] per (s,b), packed half2. 32*16*64 u32 = 128 KB.
__device__ unsigned g_hkbh[SB * KK * (HH / 2)];

__device__ __forceinline__ u64 pk2(float lo, float hi) {
    u64 r; asm("mov.b64 %0, {%1, %2};" : "=l"(r) : "f"(lo), "f"(hi)); return r;
}
__device__ __forceinline__ void upk2(float& lo, float& hi, u64 v) {
    asm("mov.b64 {%0, %1}, %2;" : "=f"(lo), "=f"(hi) : "l"(v));
}
__device__ __forceinline__ u64 fma2(u64 a, u64 b, u64 c) {
    u64 r; asm("fma.rn.f32x2 %0, %1, %2, %3;" : "=l"(r) : "l"(a), "l"(b), "l"(c)); return r;
}
__device__ __forceinline__ __half2 tanh2(__half2 v) {
    unsigned vi = *reinterpret_cast<unsigned*>(&v), yi;
    asm("tanh.approx.f16x2 %0, %1;" : "=r"(yi) : "r"(vi));
    return *reinterpret_cast<__half2*>(&yi);
}
__device__ __forceinline__ __half2 asH2(unsigned u) { return *reinterpret_cast<__half2*>(&u); }
__device__ __forceinline__ unsigned h2bits(__half2 h) { return *reinterpret_cast<unsigned*>(&h); }

// ---------------------------------------------------------------------------
// Prep: hkbh[sb,k,h/2] = half2( sum_d mu*Wm + tau*Wt + b1 )
// ---------------------------------------------------------------------------
__global__ void prep_kernel(const float* __restrict__ mu,
                            const float* __restrict__ tau,
                            const float* __restrict__ W1,
                            const float* __restrict__ b1) {
    int k  = blockIdx.x;
    int sb = blockIdx.y;
    int t  = threadIdx.x;               // 0..63 -> h pair (2t, 2t+1)
    const float* mur  = mu  + (sb * KK + k) * DD;
    const float* taur = tau + (sb * KK + k) * DD;
    int h0 = 2 * t, h1 = 2 * t + 1;
    float s0 = b1[h0], s1 = b1[h1];
    #pragma unroll
    for (int d = 0; d < DD; d++) {
        float m = mur[d], ta = taur[d];
        s0 = fmaf(m,  W1[(DD     + d) * HH + h0], s0);
        s1 = fmaf(m,  W1[(DD     + d) * HH + h1], s1);
        s0 = fmaf(ta, W1[(2 * DD + d) * HH + h0], s0);
        s1 = fmaf(ta, W1[(2 * DD + d) * HH + h1], s1);
    }
    g_hkbh[(sb * KK + k) * (HH / 2) + t] = h2bits(__floats2half2_rn(s0, s1));
}

// ---------------------------------------------------------------------------
// Main: block = 8 warps x 64 tokens. Warp w owns h-slice [16w,16w+16);
// thread register-blocks TT=2 token groups. Wx via warp-uniform __ldg
// (L1-resident, reused by all blocks). No acc registers: each (t,k) result
// is stored straight to padded part_s; ONE sync; reduce + softmax.
// ---------------------------------------------------------------------------
__global__ __launch_bounds__(TPB, 3)
void main_kernel(const float* __restrict__ x,
                 const float* __restrict__ W1,
                 const float* __restrict__ W2,
                 float* __restrict__ out) {
    __shared__ unsigned hkb_s[KK * (HH / 2)];        //  4 KB
    __shared__ float    xT_s[DD][TOKPB + 1];         //  8.1 KB (padded rows)
    __shared__ float    part_s[NW][TOKPB][KK + 1];   // 34.8 KB (stride-17 rows)

    const int tid  = threadIdx.x;
    const int w    = tid >> 5;                       // warp id = h-slice
    const int lane = tid & 31;
    const int sb   = blockIdx.y;
    const int tokb = blockIdx.x * TOKPB;
    const int h0   = w * 16;

    for (int i = tid; i < KK * (HH / 2); i += TPB)
        hkb_s[i] = g_hkbh[sb * KK * (HH / 2) + i];

    // Stage x transposed: xT_s[d][tok] (coalesced LDG.128, one step)
    #pragma unroll
    for (int it = 0; it < 2; it++) {
        int idx = tid + it * TPB;                    // 0..511 = 64 tok x 8 quads
        int tok = idx >> 3, q = idx & 7;
        float4 v = *reinterpret_cast<const float4*>(
            x + ((size_t)sb * NTOK + tokb + tok) * DD + q * 4);
        xT_s[q * 4 + 0][tok] = v.x; xT_s[q * 4 + 1][tok] = v.y;
        xT_s[q * 4 + 2][tok] = v.z; xT_s[q * 4 + 3][tok] = v.w;
    }
    __syncthreads();

    // ---- Phase A: hx (f32, FFMA2) for TT token groups x 16 h ----
    u64 hx2[TT][8];
    #pragma unroll
    for (int t = 0; t < TT; t++)
        #pragma unroll
        for (int j = 0; j < 8; j++) hx2[t][j] = 0ull;

    #pragma unroll
    for (int d = 0; d < DD; d++) {
        const ulonglong2* wrow =
            reinterpret_cast<const ulonglong2*>(W1 + d * HH + h0);
        ulonglong2 wa = __ldg(wrow + 0);             // warp-uniform LDG.128
        ulonglong2 wb = __ldg(wrow + 1);
        #pragma unroll
        for (int t = 0; t < TT; t++) {
            float xv = xT_s[d][t * 32 + lane];       // conflict-free LDS.32
            u64 x2 = pk2(xv, xv);
            hx2[t][0] = fma2(x2, wa.x, hx2[t][0]);
            hx2[t][1] = fma2(x2, wa.y, hx2[t][1]);
            hx2[t][2] = fma2(x2, wb.x, hx2[t][2]);
            hx2[t][3] = fma2(x2, wb.y, hx2[t][3]);
        }
        const ulonglong2* wrow2 =
            reinterpret_cast<const ulonglong2*>(W1 + d * HH + h0 + 8);
        ulonglong2 wc = __ldg(wrow2 + 0);
        ulonglong2 wd = __ldg(wrow2 + 1);
        #pragma unroll
        for (int t = 0; t < TT; t++) {
            float xv = xT_s[d][t * 32 + lane];
            u64 x2 = pk2(xv, xv);
            hx2[t][4] = fma2(x2, wc.x, hx2[t][4]);
            hx2[t][5] = fma2(x2, wc.y, hx2[t][5]);
            hx2[t][6] = fma2(x2, wd.x, hx2[t][6]);
            hx2[t][7] = fma2(x2, wd.y, hx2[t][7]);
        }
    }

    // One-time hx -> half2 (releases hx2 registers)
    unsigned hxh[TT][8];
    #pragma unroll
    for (int t = 0; t < TT; t++)
        #pragma unroll
        for (int q = 0; q < 8; q++) {
            float lo, hi;
            upk2(lo, hi, hx2[t][q]);
            hxh[t][q] = h2bits(__floats2half2_rn(lo, hi));
        }

    // W2 slice as half2 (warp-uniform LDG)
    __half2 w2h[8];
    {
        const float4* w2p = reinterpret_cast<const float4*>(W2 + h0);
        #pragma unroll
        for (int q = 0; q < 4; q++) {
            float4 wv = __ldg(w2p + q);
            w2h[2 * q + 0] = __floats2half2_rn(wv.x, wv.y);
            w2h[2 * q + 1] = __floats2half2_rn(wv.z, wv.w);
        }
    }

    // ---- Phase B: all-f16 inner loop, results straight to smem ----
    #pragma unroll
    for (int k = 0; k < KK; k++) {
        const uint4* hkp = reinterpret_cast<const uint4*>(&hkb_s[k * (HH / 2) + w * 8]);
        uint4 hA = hkp[0], hB = hkp[1];              // warp-uniform LDS.128
        #pragma unroll
        for (int t = 0; t < TT; t++) {
            __half2 a0, a1, a2, a3;
            a0 = __hmul2(tanh2(__hadd2(asH2(hxh[t][0]), asH2(hA.x))), w2h[0]);
            a1 = __hmul2(tanh2(__hadd2(asH2(hxh[t][1]), asH2(hA.y))), w2h[1]);
            a2 = __hmul2(tanh2(__hadd2(asH2(hxh[t][2]), asH2(hA.z))), w2h[2]);
            a3 = __hmul2(tanh2(__hadd2(asH2(hxh[t][3]), asH2(hA.w))), w2h[3]);
            a0 = __hfma2(tanh2(__hadd2(asH2(hxh[t][4]), asH2(hB.x))), w2h[4], a0);
            a1 = __hfma2(tanh2(__hadd2(asH2(hxh[t][5]), asH2(hB.y))), w2h[5], a1);
            a2 = __hfma2(tanh2(__hadd2(asH2(hxh[t][6]), asH2(hB.z))), w2h[6], a2);
            a3 = __hfma2(tanh2(__hadd2(asH2(hxh[t][7]), asH2(hB.w))), w2h[7], a3);
            float2 f01 = __half22float2(__hadd2(a0, a1));
            float2 f23 = __half22float2(__hadd2(a2, a3));
            // stride-17 rows: bank = lane*17 mod 64, conflict-free STS.32
            part_s[w][t * 32 + lane][k] = (f01.x + f01.y) + (f23.x + f23.y);
        }
    }
    __syncthreads();

    // ---- Reduce + softmax: thread = (token = tid>>2, k-quad = tid&3) ----
    const int tok = tid >> 2;
    const int kq  = tid & 3;
    float g[4];
    #pragma unroll
    for (int j = 0; j < 4; j++) {
        int k = 4 * kq + j;
        float s = 0.f;
        #pragma unroll
        for (int ww = 0; ww < NW; ww++) s += part_s[ww][tok][k];
        g[j] = s;
    }

    float m = fmaxf(fmaxf(g[0], g[1]), fmaxf(g[2], g[3]));
    m = fmaxf(m, __shfl_xor_sync(0xffffffffu, m, 1));
    m = fmaxf(m, __shfl_xor_sync(0xffffffffu, m, 2));

    float e0 = __expf(g[0] - m), e1 = __expf(g[1] - m);
    float e2 = __expf(g[2] - m), e3 = __expf(g[3] - m);
    float s = (e0 + e1) + (e2 + e3);
    s += __shfl_xor_sync(0xffffffffu, s, 1);
    s += __shfl_xor_sync(0xffffffffu, s, 2);
    float inv = __fdividef(1.f, s);

    float4 o;
    o.x = e0 * inv; o.y = e1 * inv; o.z = e2 * inv; o.w = e3 * inv;
    reinterpret_cast<float4*>(out + ((size_t)sb * NTOK + tokb + tok) * KK)[kq] = o;
}

extern "C" void kernel_launch(void* const* d_in, const int* in_sizes, int n_in,
                              void* d_out, int out_size) {
    const float* x   = (const float*)d_in[0];
    const float* mu  = (const float*)d_in[1];
    const float* tau = (const float*)d_in[2];
    const float* W1  = (const float*)d_in[3];
    const float* b1  = (const float*)d_in[4];
    const float* W2  = (const float*)d_in[5];
    // d_in[6] = b2: cancels in softmax, unused.
    float* out = (float*)d_out;

    prep_kernel<<<dim3(KK, SB), HH / 2>>>(mu, tau, W1, b1);
    main_kernel<<<dim3(NTOK / TOKPB, SB), TPB>>>(x, W1, W2, out);
}